// round 3
// baseline (speedup 1.0000x reference)
#include <cuda_runtime.h>

#define N_NODES 100000
#define E_EDGES 3200000
#define IN_DIM  256
#define OUT_DIM 64
#define LN_EPS  1e-5f
#define NEG_SLOPE 0.01f

// Scratch (no allocations allowed -> __device__ globals). 16B-aligned for v4 ops.
__device__ __align__(16) float g_deg[N_NODES];
__device__ __align__(16) float g_hs [N_NODES * OUT_DIM];  // (x@W)*rsqrt(deg[row])
__device__ __align__(16) float g_acc[N_NODES * OUT_DIM];  // accumulator, init = g_hs

// ---------------------------------------------------------------------------
// 1) deg init (self-loop weight 1)
// ---------------------------------------------------------------------------
__global__ void k_init_deg() {
    int i = blockIdx.x * blockDim.x + threadIdx.x;
    if (i < N_NODES) g_deg[i] = 1.0f;
}

// ---------------------------------------------------------------------------
// 2) deg[dst] += ew   (spread atomics, L2-resident 400KB)
// ---------------------------------------------------------------------------
__global__ void k_deg_scatter(const int* __restrict__ ei, const float* __restrict__ ew) {
    int e = blockIdx.x * blockDim.x + threadIdx.x;
    if (e < E_EDGES) atomicAdd(&g_deg[ei[E_EDGES + e]], ew[e]);
}

// ---------------------------------------------------------------------------
// 3) GEMM: hs = (x @ W) * rsqrt(deg),  acc = hs
//    64 rows/block, 256 threads, thread = 4x4 tile. W (64KB) + x tile (64KB) smem.
// ---------------------------------------------------------------------------
#define GEMM_ROWS 64
__global__ void k_gemm(const float* __restrict__ x, const float* __restrict__ W) {
    extern __shared__ float sm[];
    float* ws = sm;                          // [256*64]
    float* xs = sm + IN_DIM * OUT_DIM;       // [64*256]
    const int tid  = threadIdx.x;
    const int row0 = blockIdx.x * GEMM_ROWS;

    // load W: 16384 floats = 4096 float4
    {
        const float4* Wv = (const float4*)W;
        float4* wsv = (float4*)ws;
        #pragma unroll
        for (int i = 0; i < 16; i++) wsv[tid + 256 * i] = Wv[tid + 256 * i];
    }
    // load x tile: 64 rows x 256 cols = 4096 float4 (zero-pad OOB rows)
    {
        float4* xsv = (float4*)xs;
        #pragma unroll
        for (int i = 0; i < 16; i++) {
            int idx = tid + 256 * i;
            int r   = idx >> 6;
            int gr  = row0 + r;
            xsv[idx] = (gr < N_NODES) ? ((const float4*)x)[(size_t)gr * 64 + (idx & 63)]
                                      : make_float4(0.f, 0.f, 0.f, 0.f);
        }
    }
    __syncthreads();

    const int tr = tid >> 4;
    const int tc = tid & 15;
    float acc[4][4];
    #pragma unroll
    for (int i = 0; i < 4; i++)
        #pragma unroll
        for (int j = 0; j < 4; j++) acc[i][j] = 0.f;

    #pragma unroll 8
    for (int k = 0; k < IN_DIM; k++) {
        float4 wv = *(const float4*)&ws[k * OUT_DIM + (tc << 2)];
        #pragma unroll
        for (int i = 0; i < 4; i++) {
            float xv = xs[(tr * 4 + i) * IN_DIM + k];
            acc[i][0] = fmaf(xv, wv.x, acc[i][0]);
            acc[i][1] = fmaf(xv, wv.y, acc[i][1]);
            acc[i][2] = fmaf(xv, wv.z, acc[i][2]);
            acc[i][3] = fmaf(xv, wv.w, acc[i][3]);
        }
    }

    #pragma unroll
    for (int i = 0; i < 4; i++) {
        int gr = row0 + tr * 4 + i;
        if (gr < N_NODES) {
            float rs = rsqrtf(g_deg[gr]);
            #pragma unroll
            for (int j = 0; j < 4; j++) {
                float v = acc[i][j] * rs;
                int o = gr * OUT_DIM + (tc << 2) + j;
                g_hs[o]  = v;
                g_acc[o] = v;   // self-loop term (final *dinv[dst] in finalize)
            }
        }
    }
}

// ---------------------------------------------------------------------------
// 4) edge scatter: acc[dst] += hs[src] * ew
//    ONE thread per edge; 16x ld.v4 + 16x red.global.add.v4.f32 (sm_90+).
//    ~11 L1tex wavefronts per edge vs ~128 in the 16-thread/scalar-atomic form.
// ---------------------------------------------------------------------------
__device__ __forceinline__ void red_v4(float* addr, float a, float b, float c, float d) {
    asm volatile("red.global.add.v4.f32 [%0], {%1, %2, %3, %4};"
                 :: "l"(addr), "f"(a), "f"(b), "f"(c), "f"(d) : "memory");
}

__global__ void __launch_bounds__(256) k_scatter(const int* __restrict__ ei,
                                                 const float* __restrict__ ew) {
    int e = blockIdx.x * blockDim.x + threadIdx.x;
    if (e >= E_EDGES) return;

    const int   src = ei[e];
    const int   dst = ei[E_EDGES + e];
    const float w   = ew[e];

    const float4* __restrict__ m = (const float4*)&g_hs[src * OUT_DIM];
    float*                     a = &g_acc[dst * OUT_DIM];

    #pragma unroll
    for (int g = 0; g < 4; g++) {
        float4 m0 = m[g * 4 + 0];
        float4 m1 = m[g * 4 + 1];
        float4 m2 = m[g * 4 + 2];
        float4 m3 = m[g * 4 + 3];
        red_v4(a + g * 16 + 0,  m0.x * w, m0.y * w, m0.z * w, m0.w * w);
        red_v4(a + g * 16 + 4,  m1.x * w, m1.y * w, m1.z * w, m1.w * w);
        red_v4(a + g * 16 + 8,  m2.x * w, m2.y * w, m2.z * w, m2.w * w);
        red_v4(a + g * 16 + 12, m3.x * w, m3.y * w, m3.z * w, m3.w * w);
    }
}

// ---------------------------------------------------------------------------
// 5) finalize: y = acc*dinv + b -> leaky_relu -> LayerNorm -> out
//    one warp per node, 2 cols per lane
// ---------------------------------------------------------------------------
__global__ void k_finalize(const float* __restrict__ b, const float* __restrict__ gamma,
                           const float* __restrict__ beta, float* __restrict__ out) {
    int gw   = (blockIdx.x * blockDim.x + threadIdx.x) >> 5;
    int lane = threadIdx.x & 31;
    if (gw >= N_NODES) return;

    float dinv = rsqrtf(g_deg[gw]);
    int c0 = lane << 1;

    float2 a = *(const float2*)&g_acc[gw * OUT_DIM + c0];
    float y0 = a.x * dinv + b[c0];
    float y1 = a.y * dinv + b[c0 + 1];
    y0 = (y0 >= 0.f) ? y0 : NEG_SLOPE * y0;
    y1 = (y1 >= 0.f) ? y1 : NEG_SLOPE * y1;

    float s  = y0 + y1;
    float sq = y0 * y0 + y1 * y1;
    #pragma unroll
    for (int off = 16; off > 0; off >>= 1) {
        s  += __shfl_xor_sync(0xFFFFFFFFu, s,  off);
        sq += __shfl_xor_sync(0xFFFFFFFFu, sq, off);
    }
    float mu  = s * (1.f / 64.f);
    float var = sq * (1.f / 64.f) - mu * mu;
    float inv = rsqrtf(var + LN_EPS);

    float o0 = (y0 - mu) * inv * gamma[c0]     + beta[c0];
    float o1 = (y1 - mu) * inv * gamma[c0 + 1] + beta[c0 + 1];
    float2 r; r.x = o0; r.y = o1;
    *(float2*)&out[gw * OUT_DIM + c0] = r;
}

// ---------------------------------------------------------------------------
extern "C" void kernel_launch(void* const* d_in, const int* in_sizes, int n_in,
                              void* d_out, int out_size) {
    const float* x     = (const float*)d_in[0];
    const int*   ei    = (const int*)  d_in[1];
    const float* ew    = (const float*)d_in[2];
    const float* W     = (const float*)d_in[3];
    const float* b     = (const float*)d_in[4];
    const float* gamma = (const float*)d_in[5];
    const float* beta  = (const float*)d_in[6];
    float* out = (float*)d_out;

    cudaFuncSetAttribute(k_gemm, cudaFuncAttributeMaxDynamicSharedMemorySize,
                         (IN_DIM * OUT_DIM + GEMM_ROWS * IN_DIM) * (int)sizeof(float));

    k_init_deg   <<<(N_NODES + 255) / 256, 256>>>();
    k_deg_scatter<<<(E_EDGES + 255) / 256, 256>>>(ei, ew);
    k_gemm       <<<(N_NODES + GEMM_ROWS - 1) / GEMM_ROWS, 256,
                    (IN_DIM * OUT_DIM + GEMM_ROWS * IN_DIM) * sizeof(float)>>>(x, W);
    k_scatter    <<<(E_EDGES + 255) / 256, 256>>>(ei, ew);
    k_finalize   <<<(N_NODES * 32 + 255) / 256, 256>>>(b, gamma, beta, out);
}

// round 4
// speedup vs baseline: 2.5355x; 2.5355x over previous
#include <cuda_runtime.h>

#define N_NODES 100000
#define E_EDGES 3200000
#define IN_DIM  256
#define OUT_DIM 64
#define LN_EPS  1e-5f
#define NEG_SLOPE 0.01f

// Scratch (no allocations allowed -> __device__ globals). 16B-aligned for v4 ops.
__device__ __align__(16) float g_deg[N_NODES];
__device__ __align__(16) float g_hs [N_NODES * OUT_DIM];  // (x@W)*rsqrt(deg[row])
__device__ __align__(16) float g_acc[N_NODES * OUT_DIM];  // accumulator, init = g_hs

// ---------------------------------------------------------------------------
// 1) deg init (self-loop weight 1)
// ---------------------------------------------------------------------------
__global__ void k_init_deg() {
    int i = blockIdx.x * blockDim.x + threadIdx.x;
    if (i < N_NODES) g_deg[i] = 1.0f;
}

// ---------------------------------------------------------------------------
// 2) deg[dst] += ew   (spread atomics, L2-resident 400KB)
// ---------------------------------------------------------------------------
__global__ void k_deg_scatter(const int* __restrict__ ei, const float* __restrict__ ew) {
    int e = blockIdx.x * blockDim.x + threadIdx.x;
    if (e < E_EDGES) atomicAdd(&g_deg[ei[E_EDGES + e]], ew[e]);
}

// ---------------------------------------------------------------------------
// 3) GEMM: hs = (x @ W) * rsqrt(deg),  acc = hs
//    64 rows/block, 256 threads, thread = 4x4 tile. W (64KB) + x tile (64KB) smem.
// ---------------------------------------------------------------------------
#define GEMM_ROWS 64
__global__ void k_gemm(const float* __restrict__ x, const float* __restrict__ W) {
    extern __shared__ float sm[];
    float* ws = sm;                          // [256*64]
    float* xs = sm + IN_DIM * OUT_DIM;       // [64*256]
    const int tid  = threadIdx.x;
    const int row0 = blockIdx.x * GEMM_ROWS;

    // load W: 16384 floats = 4096 float4
    {
        const float4* Wv = (const float4*)W;
        float4* wsv = (float4*)ws;
        #pragma unroll
        for (int i = 0; i < 16; i++) wsv[tid + 256 * i] = Wv[tid + 256 * i];
    }
    // load x tile: 64 rows x 256 cols = 4096 float4 (zero-pad OOB rows)
    {
        float4* xsv = (float4*)xs;
        #pragma unroll
        for (int i = 0; i < 16; i++) {
            int idx = tid + 256 * i;
            int r   = idx >> 6;
            int gr  = row0 + r;
            xsv[idx] = (gr < N_NODES) ? ((const float4*)x)[(size_t)gr * 64 + (idx & 63)]
                                      : make_float4(0.f, 0.f, 0.f, 0.f);
        }
    }
    __syncthreads();

    const int tr = tid >> 4;
    const int tc = tid & 15;
    float acc[4][4];
    #pragma unroll
    for (int i = 0; i < 4; i++)
        #pragma unroll
        for (int j = 0; j < 4; j++) acc[i][j] = 0.f;

    #pragma unroll 8
    for (int k = 0; k < IN_DIM; k++) {
        float4 wv = *(const float4*)&ws[k * OUT_DIM + (tc << 2)];
        #pragma unroll
        for (int i = 0; i < 4; i++) {
            float xv = xs[(tr * 4 + i) * IN_DIM + k];
            acc[i][0] = fmaf(xv, wv.x, acc[i][0]);
            acc[i][1] = fmaf(xv, wv.y, acc[i][1]);
            acc[i][2] = fmaf(xv, wv.z, acc[i][2]);
            acc[i][3] = fmaf(xv, wv.w, acc[i][3]);
        }
    }

    #pragma unroll
    for (int i = 0; i < 4; i++) {
        int gr = row0 + tr * 4 + i;
        if (gr < N_NODES) {
            float rs = rsqrtf(g_deg[gr]);
            #pragma unroll
            for (int j = 0; j < 4; j++) {
                float v = acc[i][j] * rs;
                int o = gr * OUT_DIM + (tc << 2) + j;
                g_hs[o]  = v;
                g_acc[o] = v;   // self-loop term (final *dinv[dst] in finalize)
            }
        }
    }
}

// ---------------------------------------------------------------------------
// 4) edge scatter: acc[dst] += hs[src] * ew
//    16 threads per edge (COALESCED: one edge's 256B row = 16 contiguous lanes),
//    each lane does ONE ld.float4 + ONE red.global.add.v4.f32.
//    vs R1: same coalesced loads, but 16 red lane-ops/edge instead of 64 scalar.
// ---------------------------------------------------------------------------
__device__ __forceinline__ void red_v4(float* addr, float a, float b, float c, float d) {
    asm volatile("red.global.add.v4.f32 [%0], {%1, %2, %3, %4};"
                 :: "l"(addr), "f"(a), "f"(b), "f"(c), "f"(d) : "memory");
}

__global__ void __launch_bounds__(256) k_scatter(const int* __restrict__ ei,
                                                 const float* __restrict__ ew) {
    int t = blockIdx.x * blockDim.x + threadIdx.x;
    int e = t >> 4;
    if (e >= E_EDGES) return;
    int part = t & 15;

    const int   src = ei[e];
    const int   dst = ei[E_EDGES + e];
    const float w   = ew[e];

    float4 m = *(const float4*)&g_hs[src * OUT_DIM + (part << 2)];
    red_v4(&g_acc[dst * OUT_DIM + (part << 2)], m.x * w, m.y * w, m.z * w, m.w * w);
}

// ---------------------------------------------------------------------------
// 5) finalize: y = acc*dinv + b -> leaky_relu -> LayerNorm -> out
//    one warp per node, 2 cols per lane
// ---------------------------------------------------------------------------
__global__ void k_finalize(const float* __restrict__ b, const float* __restrict__ gamma,
                           const float* __restrict__ beta, float* __restrict__ out) {
    int gw   = (blockIdx.x * blockDim.x + threadIdx.x) >> 5;
    int lane = threadIdx.x & 31;
    if (gw >= N_NODES) return;

    float dinv = rsqrtf(g_deg[gw]);
    int c0 = lane << 1;

    float2 a = *(const float2*)&g_acc[gw * OUT_DIM + c0];
    float y0 = a.x * dinv + b[c0];
    float y1 = a.y * dinv + b[c0 + 1];
    y0 = (y0 >= 0.f) ? y0 : NEG_SLOPE * y0;
    y1 = (y1 >= 0.f) ? y1 : NEG_SLOPE * y1;

    float s  = y0 + y1;
    float sq = y0 * y0 + y1 * y1;
    #pragma unroll
    for (int off = 16; off > 0; off >>= 1) {
        s  += __shfl_xor_sync(0xFFFFFFFFu, s,  off);
        sq += __shfl_xor_sync(0xFFFFFFFFu, sq, off);
    }
    float mu  = s * (1.f / 64.f);
    float var = sq * (1.f / 64.f) - mu * mu;
    float inv = rsqrtf(var + LN_EPS);

    float o0 = (y0 - mu) * inv * gamma[c0]     + beta[c0];
    float o1 = (y1 - mu) * inv * gamma[c0 + 1] + beta[c0 + 1];
    float2 r; r.x = o0; r.y = o1;
    *(float2*)&out[gw * OUT_DIM + c0] = r;
}

// ---------------------------------------------------------------------------
extern "C" void kernel_launch(void* const* d_in, const int* in_sizes, int n_in,
                              void* d_out, int out_size) {
    const float* x     = (const float*)d_in[0];
    const int*   ei    = (const int*)  d_in[1];
    const float* ew    = (const float*)d_in[2];
    const float* W     = (const float*)d_in[3];
    const float* b     = (const float*)d_in[4];
    const float* gamma = (const float*)d_in[5];
    const float* beta  = (const float*)d_in[6];
    float* out = (float*)d_out;

    cudaFuncSetAttribute(k_gemm, cudaFuncAttributeMaxDynamicSharedMemorySize,
                         (IN_DIM * OUT_DIM + GEMM_ROWS * IN_DIM) * (int)sizeof(float));

    k_init_deg   <<<(N_NODES + 255) / 256, 256>>>();
    k_deg_scatter<<<(E_EDGES + 255) / 256, 256>>>(ei, ew);
    k_gemm       <<<(N_NODES + GEMM_ROWS - 1) / GEMM_ROWS, 256,
                    (IN_DIM * OUT_DIM + GEMM_ROWS * IN_DIM) * sizeof(float)>>>(x, W);
    k_scatter    <<<((long long)E_EDGES * 16 + 255) / 256, 256>>>(ei, ew);
    k_finalize   <<<(N_NODES * 32 + 255) / 256, 256>>>(b, gamma, beta, out);
}